// round 1
// baseline (speedup 1.0000x reference)
#include <cuda_runtime.h>
#include <cstddef>

#define T_DIM 2048
#define B_DIM 64
#define I_DIM 256
#define H_DIM 256
#define M_DIM (T_DIM * B_DIM)   // 131072 rows
#define N_DIM (3 * H_DIM)       // 768 cols (r,z,n gates)
#define K_DIM I_DIM             // 256

// Scratch: gate pre-activations gx[T*B][3H] (402 MB) and transposed weights.
__device__ float g_gx[(size_t)M_DIM * N_DIM];
__device__ float g_Wt[(size_t)K_DIM * N_DIM];   // Wt[k][n] = W_ih[n][k]

// ---------------------------------------------------------------------------
// Tiny transpose: W_ih [768, 256] -> g_Wt [256, 768]
// ---------------------------------------------------------------------------
__global__ void transpose_W_kernel(const float* __restrict__ W) {
    int idx = blockIdx.x * blockDim.x + threadIdx.x;
    if (idx < N_DIM * K_DIM) {
        int n = idx / K_DIM;
        int k = idx - n * K_DIM;
        g_Wt[(size_t)k * N_DIM + n] = W[idx];
    }
}

// ---------------------------------------------------------------------------
// fp32 SIMT GEMM: g_gx[m][n] = sum_k x[m][k] * W_ih[n][k] + b_ih[n]
// BM=128, BN=64, BK=32, 256 threads, 8x4 microtile per thread.
// As kept [m][k] (k-contiguous, float4 loads both directions).
// Ws kept [k][n] (n-contiguous) from pre-transposed g_Wt -> conflict-free.
// ---------------------------------------------------------------------------
#define BM 128
#define BN 64
#define BK 32

__global__ __launch_bounds__(256, 2)
void gemm_kernel(const float* __restrict__ A, const float* __restrict__ bias) {
    __shared__ float As[BM][BK];      // [m][k]
    __shared__ float Ws[BK][BN];      // [k][n]

    const int bm = blockIdx.x;        // 0..1023
    const int bn = blockIdx.y;        // 0..11
    const int tid = threadIdx.x;
    const int rg = tid >> 4;          // 0..15 : row group (8 rows each)
    const int cg = tid & 15;          // 0..15 : col group (4 cols each)

    const float* Ablk = A + (size_t)bm * BM * K_DIM;
    const int ncol0 = bn * BN + cg * 4;

    float acc[8][4];
#pragma unroll
    for (int i = 0; i < 8; i++)
#pragma unroll
        for (int j = 0; j < 4; j++) acc[i][j] = 0.f;

    for (int k0 = 0; k0 < K_DIM; k0 += BK) {
        // Load A tile 128x32: 1024 float4, 4 per thread (k-contiguous)
#pragma unroll
        for (int j = 0; j < 4; j++) {
            int f = tid + 256 * j;
            int row = f >> 3;            // 0..127
            int kq = f & 7;              // 0..7 (float4 along k)
            float4 v = *(const float4*)(Ablk + (size_t)row * K_DIM + k0 + kq * 4);
            *(float4*)(&As[row][kq * 4]) = v;
        }
        // Load W tile 32x64 from g_Wt: 512 float4, 2 per thread (n-contiguous)
#pragma unroll
        for (int j = 0; j < 2; j++) {
            int f = tid + 256 * j;
            int kk = f >> 4;             // 0..31
            int nq = f & 15;             // 0..15
            float4 v = *(const float4*)(g_Wt + (size_t)(k0 + kk) * N_DIM + bn * BN + nq * 4);
            *(float4*)(&Ws[kk][nq * 4]) = v;
        }
        __syncthreads();

#pragma unroll
        for (int kq = 0; kq < BK / 4; kq++) {
            float a[8][4];
#pragma unroll
            for (int i = 0; i < 8; i++)
                *(float4*)(a[i]) = *(const float4*)(&As[rg * 8 + i][kq * 4]);
#pragma unroll
            for (int kk = 0; kk < 4; kk++) {
                float b[4];
                *(float4*)(b) = *(const float4*)(&Ws[kq * 4 + kk][cg * 4]);
#pragma unroll
                for (int i = 0; i < 8; i++) {
#pragma unroll
                    for (int jn = 0; jn < 4; jn++)
                        acc[i][jn] += a[i][kk] * b[jn];
                }
            }
        }
        __syncthreads();
    }

    float4 b4 = *(const float4*)(bias + ncol0);
#pragma unroll
    for (int i = 0; i < 8; i++) {
        size_t row = (size_t)bm * BM + rg * 8 + i;
        float4 o;
        o.x = acc[i][0] + b4.x;
        o.y = acc[i][1] + b4.y;
        o.z = acc[i][2] + b4.z;
        o.w = acc[i][3] + b4.w;
        *(float4*)(g_gx + row * N_DIM + ncol0) = o;
    }
}

// ---------------------------------------------------------------------------
// Diagonal-recurrence GRU scan. One thread per (b,h): 16384 independent chains.
// ---------------------------------------------------------------------------
__device__ __forceinline__ float sigf(float x) {
    return __fdividef(1.f, 1.f + __expf(-x));
}
__device__ __forceinline__ float tanhf_fast(float x) {
    // tanh(x) = 2*sigmoid(2x) - 1
    return __fdividef(2.f, 1.f + __expf(-2.f * x)) - 1.f;
}

__global__ __launch_bounds__(256, 1)
void scan_kernel(const float* __restrict__ b_hh, const float* __restrict__ w_hh,
                 float* __restrict__ out, long long out_size) {
    const int idx = blockIdx.x * blockDim.x + threadIdx.x;  // 0..16383
    const int b = idx >> 8;        // batch
    const int h = idx & (H_DIM - 1);

    const float w_hr = w_hh[h];
    const float w_hz = w_hh[H_DIM + h];
    const float w_hn = w_hh[2 * H_DIM + h];
    const float b_hr = b_hh[h];
    const float b_hz = b_hh[H_DIM + h];
    const float b_hn = b_hh[2 * H_DIM + h];

    const float* gx = g_gx + (size_t)b * N_DIM + h;
    const size_t rowstride = (size_t)B_DIM * N_DIM;  // 49152

    float hv = 0.f;
    // prefetch t = 0
    float xr = gx[0];
    float xz = gx[H_DIM];
    float xn = gx[2 * H_DIM];

    for (int t = 0; t < T_DIM; t++) {
        float pxr = 0.f, pxz = 0.f, pxn = 0.f;
        if (t + 1 < T_DIM) {
            const float* nxt = gx + (size_t)(t + 1) * rowstride;
            pxr = nxt[0];
            pxz = nxt[H_DIM];
            pxn = nxt[2 * H_DIM];
        }
        float r = sigf(xr + w_hr * hv + b_hr);
        float z = sigf(xz + w_hz * hv + b_hz);
        float n = tanhf_fast(xn + r * (w_hn * hv + b_hn));
        hv = (1.f - z) * n + z * hv;
        out[(size_t)t * (B_DIM * H_DIM) + idx] = hv;
        xr = pxr; xz = pxz; xn = pxn;
    }
    // final hidden state h_n appended after out[T,B,H]
    if (out_size > (long long)T_DIM * B_DIM * H_DIM)
        out[(size_t)T_DIM * B_DIM * H_DIM + idx] = hv;
}

// ---------------------------------------------------------------------------
// Launch
// ---------------------------------------------------------------------------
extern "C" void kernel_launch(void* const* d_in, const int* in_sizes, int n_in,
                              void* d_out, int out_size) {
    const float* x    = (const float*)d_in[0];   // [T, B, I]
    const float* W_ih = (const float*)d_in[1];   // [3H, I]
    const float* b_ih = (const float*)d_in[2];   // [3H]
    const float* b_hh = (const float*)d_in[3];   // [3H]
    const float* w_hh = (const float*)d_in[4];   // [3, H]
    float* out = (float*)d_out;

    transpose_W_kernel<<<(N_DIM * K_DIM + 255) / 256, 256>>>(W_ih);

    dim3 grid(M_DIM / BM, N_DIM / BN);  // (1024, 12)
    gemm_kernel<<<grid, 256>>>(x, b_ih);

    scan_kernel<<<(B_DIM * H_DIM) / 256, 256>>>(b_hh, w_hh, out, (long long)out_size);
}

// round 3
// speedup vs baseline: 1.5443x; 1.5443x over previous
#include <cuda_runtime.h>
#include <cuda_bf16.h>
#include <cstdint>
#include <cstddef>

#define T_DIM 2048
#define B_DIM 64
#define I_DIM 256
#define H_DIM 256
#define M_DIM (T_DIM * B_DIM)   // 131072
#define N_DIM (3 * H_DIM)       // 768
#define K_DIM I_DIM             // 256

// ---------------------------------------------------------------------------
// Device scratch
// ---------------------------------------------------------------------------
__device__ float g_gx[(size_t)M_DIM * N_DIM];                 // gate preacts
__device__ __nv_bfloat16 g_Xhi[(size_t)M_DIM * K_DIM];
__device__ __nv_bfloat16 g_Xlo[(size_t)M_DIM * K_DIM];
__device__ __nv_bfloat16 g_Whi[(size_t)N_DIM * K_DIM];
__device__ __nv_bfloat16 g_Wlo[(size_t)N_DIM * K_DIM];

// ---------------------------------------------------------------------------
// Helpers
// ---------------------------------------------------------------------------
__device__ __forceinline__ uint32_t smem_to_u32(const void* p) {
    uint32_t a;
    asm("{ .reg .u64 t; cvta.to.shared.u64 t, %1; cvt.u32.u64 %0, t; }" : "=r"(a) : "l"(p));
    return a;
}
__device__ __forceinline__ void cp16(uint32_t dst, const void* src) {
    asm volatile("cp.async.cg.shared.global [%0], [%1], 16;" :: "r"(dst), "l"(src));
}
__device__ __forceinline__ uint32_t lds32(uint32_t a) {
    uint32_t v;
    asm volatile("ld.shared.b32 %0, [%1];" : "=r"(v) : "r"(a));
    return v;
}
__device__ __forceinline__ void mma16816(float* c, const uint32_t* a, const uint32_t* b) {
    asm volatile(
        "mma.sync.aligned.m16n8k16.row.col.f32.bf16.bf16.f32 "
        "{%0,%1,%2,%3}, {%4,%5,%6,%7}, {%8,%9}, {%0,%1,%2,%3};"
        : "+f"(c[0]), "+f"(c[1]), "+f"(c[2]), "+f"(c[3])
        : "r"(a[0]), "r"(a[1]), "r"(a[2]), "r"(a[3]), "r"(b[0]), "r"(b[1]));
}

// ---------------------------------------------------------------------------
// Convert: fp32 -> (bf16 hi, bf16 lo) for x and W
// ---------------------------------------------------------------------------
__device__ __forceinline__ uint32_t pack_bf2(__nv_bfloat16 a, __nv_bfloat16 b) {
    __nv_bfloat162 t(a, b);
    return *reinterpret_cast<uint32_t*>(&t);
}

__global__ void convert_kernel(const float* __restrict__ x, const float* __restrict__ W) {
    const int n1 = (M_DIM * K_DIM) / 4;
    const int n2 = (N_DIM * K_DIM) / 4;
    int idx = blockIdx.x * blockDim.x + threadIdx.x;
    const float4* src;
    __nv_bfloat16 *dhi, *dlo;
    int pos;
    if (idx < n1) { src = (const float4*)x; dhi = g_Xhi; dlo = g_Xlo; pos = idx; }
    else if (idx < n1 + n2) { src = (const float4*)W; dhi = g_Whi; dlo = g_Wlo; pos = idx - n1; }
    else return;

    float4 v = src[pos];
    __nv_bfloat16 h0 = __float2bfloat16(v.x), h1 = __float2bfloat16(v.y);
    __nv_bfloat16 h2 = __float2bfloat16(v.z), h3 = __float2bfloat16(v.w);
    __nv_bfloat16 l0 = __float2bfloat16(v.x - __bfloat162float(h0));
    __nv_bfloat16 l1 = __float2bfloat16(v.y - __bfloat162float(h1));
    __nv_bfloat16 l2 = __float2bfloat16(v.z - __bfloat162float(h2));
    __nv_bfloat16 l3 = __float2bfloat16(v.w - __bfloat162float(h3));
    uint2 ho; ho.x = pack_bf2(h0, h1); ho.y = pack_bf2(h2, h3);
    uint2 lo; lo.x = pack_bf2(l0, l1); lo.y = pack_bf2(l2, l3);
    ((uint2*)dhi)[pos] = ho;
    ((uint2*)dlo)[pos] = lo;
}

// ---------------------------------------------------------------------------
// HMMA GEMM: gx[131072, 768] = X @ W^T + b_ih, 3-term bf16 split.
// CTA tile 128x128, BK=32, 8 warps (warp tile 32x64), 2-stage cp.async.
// Smem rows padded to 80B (stride 40 bf16) -> conflict-free LDS.32 frag loads.
// ---------------------------------------------------------------------------
#define ROWB 80                       // bytes per smem row (64B data + 16B pad)
#define TILE_BYTES (128 * ROWB)       // 10240
#define STAGE_BYTES (4 * TILE_BYTES)  // Ah, Al, Bh, Bl = 40960
#define GEMM_SMEM (2 * STAGE_BYTES)   // 81920

__device__ __forceinline__ void fill_stage(uint32_t base, int c, size_t m0, int n0) {
    const int tid = threadIdx.x;
    const int k0 = c * 32;
#pragma unroll
    for (int i = 0; i < 2; i++) {
        int v = tid + (i << 8);          // 0..511
        int row = v >> 2, seg = v & 3;   // 128 rows x 4 16B-segments
        uint32_t so = row * ROWB + seg * 16;
        size_t aoff = (m0 + row) * K_DIM + k0 + seg * 8;
        size_t boff = (size_t)(n0 + row) * K_DIM + k0 + seg * 8;
        cp16(base + so, g_Xhi + aoff);
        cp16(base + TILE_BYTES + so, g_Xlo + aoff);
        cp16(base + 2 * TILE_BYTES + so, g_Whi + boff);
        cp16(base + 3 * TILE_BYTES + so, g_Wlo + boff);
    }
}

__global__ __launch_bounds__(256, 2)
void gemm_hmma_kernel(const float* __restrict__ bias) {
    extern __shared__ __align__(16) char smem[];
    uint32_t sb = smem_to_u32(smem);

    const int tid = threadIdx.x;
    const int wid = tid >> 5, lane = tid & 31;
    const int g = lane >> 2, t = lane & 3;
    const int warp_m = wid & 3;          // 4 M-slices of 32
    const int warp_n = wid >> 2;         // 2 N-slices of 64
    const int nx = blockIdx.x;           // 0..5  (fast: A-slab shared in L2)
    const size_t m0 = (size_t)blockIdx.y * 128;
    const int n0 = nx * 128;

    float acc[2][8][4];
#pragma unroll
    for (int mi = 0; mi < 2; mi++)
#pragma unroll
        for (int ni = 0; ni < 8; ni++)
#pragma unroll
            for (int j = 0; j < 4; j++) acc[mi][ni][j] = 0.f;

    // prologue: chunks 0,1
    fill_stage(sb, 0, m0, n0);
    asm volatile("cp.async.commit_group;" ::: "memory");
    fill_stage(sb + STAGE_BYTES, 1, m0, n0);
    asm volatile("cp.async.commit_group;" ::: "memory");

    for (int c = 0; c < 8; c++) {
        const int s = c & 1;
        if (c < 6) asm volatile("cp.async.wait_group 1;" ::: "memory");
        else       asm volatile("cp.async.wait_group 0;" ::: "memory");
        __syncthreads();

        const uint32_t Ah = sb + s * STAGE_BYTES;
        const uint32_t Al = Ah + TILE_BYTES;
        const uint32_t Bh = Ah + 2 * TILE_BYTES;
        const uint32_t Bl = Ah + 3 * TILE_BYTES;

#pragma unroll
        for (int ks = 0; ks < 2; ks++) {
            const int kb = ks * 32;      // 16 bf16 = 32B per k-step
            uint32_t ah[2][4], al[2][4], bb[8][2];
            // A fragments (hi and lo)
#pragma unroll
            for (int mi = 0; mi < 2; mi++) {
                int r = warp_m * 32 + mi * 16;
                uint32_t b0 = (r + g) * ROWB + t * 4 + kb;
                uint32_t b1 = (r + g + 8) * ROWB + t * 4 + kb;
                ah[mi][0] = lds32(Ah + b0);  ah[mi][1] = lds32(Ah + b1);
                ah[mi][2] = lds32(Ah + b0 + 16); ah[mi][3] = lds32(Ah + b1 + 16);
                al[mi][0] = lds32(Al + b0);  al[mi][1] = lds32(Al + b1);
                al[mi][2] = lds32(Al + b0 + 16); al[mi][3] = lds32(Al + b1 + 16);
            }
            // B-hi fragments; terms Ah*Bh and Al*Bh
#pragma unroll
            for (int ni = 0; ni < 8; ni++) {
                uint32_t b0 = (warp_n * 64 + ni * 8 + g) * ROWB + t * 4 + kb;
                bb[ni][0] = lds32(Bh + b0);
                bb[ni][1] = lds32(Bh + b0 + 16);
            }
#pragma unroll
            for (int mi = 0; mi < 2; mi++)
#pragma unroll
                for (int ni = 0; ni < 8; ni++) {
                    mma16816(acc[mi][ni], ah[mi], bb[ni]);
                    mma16816(acc[mi][ni], al[mi], bb[ni]);
                }
            // B-lo fragments; term Ah*Bl
#pragma unroll
            for (int ni = 0; ni < 8; ni++) {
                uint32_t b0 = (warp_n * 64 + ni * 8 + g) * ROWB + t * 4 + kb;
                bb[ni][0] = lds32(Bl + b0);
                bb[ni][1] = lds32(Bl + b0 + 16);
            }
#pragma unroll
            for (int mi = 0; mi < 2; mi++)
#pragma unroll
                for (int ni = 0; ni < 8; ni++)
                    mma16816(acc[mi][ni], ah[mi], bb[ni]);
        }
        __syncthreads();                 // all warps done reading stage s
        if (c + 2 < 8) {
            fill_stage(sb + s * STAGE_BYTES, c + 2, m0, n0);
            asm volatile("cp.async.commit_group;" ::: "memory");
        }
    }

    // Epilogue: add bias, store float2 pairs
#pragma unroll
    for (int mi = 0; mi < 2; mi++) {
        size_t row0 = m0 + warp_m * 32 + mi * 16 + g;
#pragma unroll
        for (int ni = 0; ni < 8; ni++) {
            int col = n0 + warp_n * 64 + ni * 8 + 2 * t;
            float2 bv = *(const float2*)(bias + col);
            float2 o0, o1;
            o0.x = acc[mi][ni][0] + bv.x;  o0.y = acc[mi][ni][1] + bv.y;
            o1.x = acc[mi][ni][2] + bv.x;  o1.y = acc[mi][ni][3] + bv.y;
            *(float2*)(g_gx + row0 * N_DIM + col) = o0;
            *(float2*)(g_gx + (row0 + 8) * N_DIM + col) = o1;
        }
    }
}

// ---------------------------------------------------------------------------
// Diagonal-recurrence GRU scan. One thread per (b,h): 16384 chains.
// ---------------------------------------------------------------------------
__device__ __forceinline__ float sigf(float x) {
    return __fdividef(1.f, 1.f + __expf(-x));
}
__device__ __forceinline__ float tanhf_fast(float x) {
    return __fdividef(2.f, 1.f + __expf(-2.f * x)) - 1.f;
}

__global__ __launch_bounds__(256, 1)
void scan_kernel(const float* __restrict__ b_hh, const float* __restrict__ w_hh,
                 float* __restrict__ out, long long out_size) {
    const int idx = blockIdx.x * blockDim.x + threadIdx.x;  // 0..16383
    const int b = idx >> 8;
    const int h = idx & (H_DIM - 1);

    const float w_hr = w_hh[h];
    const float w_hz = w_hh[H_DIM + h];
    const float w_hn = w_hh[2 * H_DIM + h];
    const float b_hr = b_hh[h];
    const float b_hz = b_hh[H_DIM + h];
    const float b_hn = b_hh[2 * H_DIM + h];

    const float* gx = g_gx + (size_t)b * N_DIM + h;
    const size_t rowstride = (size_t)B_DIM * N_DIM;

    float hv = 0.f;
    float xr = gx[0];
    float xz = gx[H_DIM];
    float xn = gx[2 * H_DIM];

    for (int t = 0; t < T_DIM; t++) {
        float pxr = 0.f, pxz = 0.f, pxn = 0.f;
        if (t + 1 < T_DIM) {
            const float* nxt = gx + (size_t)(t + 1) * rowstride;
            pxr = nxt[0];
            pxz = nxt[H_DIM];
            pxn = nxt[2 * H_DIM];
        }
        float r = sigf(xr + w_hr * hv + b_hr);
        float z = sigf(xz + w_hz * hv + b_hz);
        float n = tanhf_fast(xn + r * (w_hn * hv + b_hn));
        hv = (1.f - z) * n + z * hv;
        out[(size_t)t * (B_DIM * H_DIM) + idx] = hv;
        xr = pxr; xz = pxz; xn = pxn;
    }
    if (out_size > (long long)T_DIM * B_DIM * H_DIM)
        out[(size_t)T_DIM * B_DIM * H_DIM + idx] = hv;
}

// ---------------------------------------------------------------------------
// Launch
// ---------------------------------------------------------------------------
extern "C" void kernel_launch(void* const* d_in, const int* in_sizes, int n_in,
                              void* d_out, int out_size) {
    const float* x    = (const float*)d_in[0];   // [T, B, I]
    const float* W_ih = (const float*)d_in[1];   // [3H, I]
    const float* b_ih = (const float*)d_in[2];   // [3H]
    const float* b_hh = (const float*)d_in[3];   // [3H]
    const float* w_hh = (const float*)d_in[4];   // [3, H]
    float* out = (float*)d_out;

    convert_kernel<<<32960, 256>>>(x, W_ih);

    cudaFuncSetAttribute(gemm_hmma_kernel, cudaFuncAttributeMaxDynamicSharedMemorySize, GEMM_SMEM);
    dim3 grid(N_DIM / 128, M_DIM / 128);   // (6, 1024)
    gemm_hmma_kernel<<<grid, 256, GEMM_SMEM>>>(b_ih);

    scan_kernel<<<(B_DIM * H_DIM) / 256, 256>>>(b_hh, w_hh, out, (long long)out_size);
}

// round 4
// speedup vs baseline: 2.4621x; 1.5944x over previous
#include <cuda_runtime.h>
#include <cuda_fp16.h>
#include <cstdint>
#include <cstddef>

#define T_DIM 2048
#define B_DIM 64
#define I_DIM 256
#define H_DIM 256
#define M_DIM (T_DIM * B_DIM)   // 131072
#define N_DIM (3 * H_DIM)       // 768
#define K_DIM I_DIM             // 256

// ---------------------------------------------------------------------------
// Device scratch
// ---------------------------------------------------------------------------
__device__ float g_gx[(size_t)M_DIM * N_DIM];           // gate preacts (402 MB)
__device__ __half g_Xh[(size_t)M_DIM * K_DIM];          // fp16 hi of x
__device__ __half g_Xl[(size_t)M_DIM * K_DIM];          // fp16 lo (residual) of x
__device__ __half g_Wh[(size_t)N_DIM * K_DIM];          // fp16 of W_ih

// ---------------------------------------------------------------------------
// Helpers
// ---------------------------------------------------------------------------
__device__ __forceinline__ uint32_t smem_to_u32(const void* p) {
    uint32_t a;
    asm("{ .reg .u64 t; cvta.to.shared.u64 t, %1; cvt.u32.u64 %0, t; }" : "=r"(a) : "l"(p));
    return a;
}
__device__ __forceinline__ void cp16(uint32_t dst, const void* src) {
    asm volatile("cp.async.cg.shared.global [%0], [%1], 16;" :: "r"(dst), "l"(src));
}
__device__ __forceinline__ void ldm_x4(uint32_t* r, uint32_t addr) {
    asm volatile("ldmatrix.sync.aligned.m8n8.x4.shared.b16 {%0,%1,%2,%3}, [%4];"
        : "=r"(r[0]), "=r"(r[1]), "=r"(r[2]), "=r"(r[3]) : "r"(addr));
}
__device__ __forceinline__ void mma16816(float* c, const uint32_t* a, const uint32_t* b) {
    asm volatile(
        "mma.sync.aligned.m16n8k16.row.col.f32.f16.f16.f32 "
        "{%0,%1,%2,%3}, {%4,%5,%6,%7}, {%8,%9}, {%0,%1,%2,%3};"
        : "+f"(c[0]), "+f"(c[1]), "+f"(c[2]), "+f"(c[3])
        : "r"(a[0]), "r"(a[1]), "r"(a[2]), "r"(a[3]), "r"(b[0]), "r"(b[1]));
}

// ---------------------------------------------------------------------------
// Convert: x -> fp16 hi + fp16 residual; W -> fp16
// ---------------------------------------------------------------------------
__device__ __forceinline__ uint32_t pack_h2(__half a, __half b) {
    __half2 t(a, b);
    return *reinterpret_cast<uint32_t*>(&t);
}

__global__ void convert_kernel(const float* __restrict__ x, const float* __restrict__ W) {
    const int n1 = (M_DIM * K_DIM) / 4;   // x float4s
    const int n2 = (N_DIM * K_DIM) / 4;   // W float4s
    int idx = blockIdx.x * blockDim.x + threadIdx.x;
    if (idx < n1) {
        float4 v = ((const float4*)x)[idx];
        __half h0 = __float2half_rn(v.x), h1 = __float2half_rn(v.y);
        __half h2 = __float2half_rn(v.z), h3 = __float2half_rn(v.w);
        __half l0 = __float2half_rn(v.x - __half2float(h0));
        __half l1 = __float2half_rn(v.y - __half2float(h1));
        __half l2 = __float2half_rn(v.z - __half2float(h2));
        __half l3 = __float2half_rn(v.w - __half2float(h3));
        uint2 ho; ho.x = pack_h2(h0, h1); ho.y = pack_h2(h2, h3);
        uint2 lo; lo.x = pack_h2(l0, l1); lo.y = pack_h2(l2, l3);
        ((uint2*)g_Xh)[idx] = ho;
        ((uint2*)g_Xl)[idx] = lo;
    } else if (idx < n1 + n2) {
        int pos = idx - n1;
        float4 v = ((const float4*)W)[pos];
        uint2 ho;
        ho.x = pack_h2(__float2half_rn(v.x), __float2half_rn(v.y));
        ho.y = pack_h2(__float2half_rn(v.z), __float2half_rn(v.w));
        ((uint2*)g_Wh)[pos] = ho;
    }
}

// ---------------------------------------------------------------------------
// HMMA GEMM: gx = X @ W^T + b_ih, 2-term fp16 split (Xh*Wh + Xl*Wh).
// CTA tile 128x128, BK=32, 8 warps (warp 32x64), 2-stage cp.async,
// ldmatrix.x4 fragment loads, 80B-padded rows (conflict-free).
// ---------------------------------------------------------------------------
#define ROWB 80                       // 64B data + 16B pad
#define TILE_BYTES (128 * ROWB)       // 10240
#define STAGE_BYTES (3 * TILE_BYTES)  // Ah, Al, Bh = 30720
#define GEMM_SMEM (2 * STAGE_BYTES)   // 61440

__device__ __forceinline__ void fill_stage(uint32_t base, int c, size_t m0, int n0) {
    const int tid = threadIdx.x;
    const int k0 = c * 32;
#pragma unroll
    for (int i = 0; i < 2; i++) {
        int v = tid + (i << 8);          // 0..511
        int row = v >> 2, seg = v & 3;   // 128 rows x 4 16B-segments
        uint32_t so = row * ROWB + seg * 16;
        size_t aoff = (m0 + row) * K_DIM + k0 + seg * 8;
        size_t boff = (size_t)(n0 + row) * K_DIM + k0 + seg * 8;
        cp16(base + so, g_Xh + aoff);
        cp16(base + TILE_BYTES + so, g_Xl + aoff);
        cp16(base + 2 * TILE_BYTES + so, g_Wh + boff);
    }
}

__global__ __launch_bounds__(256, 2)
void gemm_hmma_kernel(const float* __restrict__ bias) {
    extern __shared__ __align__(16) char smem[];
    uint32_t sb = smem_to_u32(smem);

    const int tid = threadIdx.x;
    const int wid = tid >> 5, lane = tid & 31;
    const int g = lane >> 2, t = lane & 3;
    const int warp_m = wid & 3;          // 4 M-slices of 32
    const int warp_n = wid >> 2;         // 2 N-slices of 64
    const size_t m0 = (size_t)blockIdx.y * 128;
    const int n0 = blockIdx.x * 128;

    // ldmatrix lane addressing (within-tile byte offsets)
    // A frag (m16xk16): lanes 0-15 -> rows m0..15 seg0; 16-31 -> rows seg1
    const uint32_t a_row = (lane & 15);
    const uint32_t a_seg = (lane >> 4);
    // B frag pair (n16xk16): 0-7 n0-7/seg0; 8-15 n0-7/seg1; 16-23 n8-15/seg0; 24-31 n8-15/seg1
    const uint32_t b_row = (lane & 7) + ((lane >> 4) << 3);
    const uint32_t b_seg = (lane >> 3) & 1;

    float acc[2][8][4];
#pragma unroll
    for (int mi = 0; mi < 2; mi++)
#pragma unroll
        for (int ni = 0; ni < 8; ni++)
#pragma unroll
            for (int j = 0; j < 4; j++) acc[mi][ni][j] = 0.f;

    fill_stage(sb, 0, m0, n0);
    asm volatile("cp.async.commit_group;" ::: "memory");
    fill_stage(sb + STAGE_BYTES, 1, m0, n0);
    asm volatile("cp.async.commit_group;" ::: "memory");

    for (int c = 0; c < 8; c++) {
        const int s = c & 1;
        if (c < 6) asm volatile("cp.async.wait_group 1;" ::: "memory");
        else       asm volatile("cp.async.wait_group 0;" ::: "memory");
        __syncthreads();

        const uint32_t Ah = sb + s * STAGE_BYTES;
        const uint32_t Al = Ah + TILE_BYTES;
        const uint32_t Bh = Ah + 2 * TILE_BYTES;

#pragma unroll
        for (int ks = 0; ks < 2; ks++) {
            const int kb = ks * 32;      // 16 fp16 = 32B
            uint32_t ah[2][4], al[2][4], bb[8][2];
#pragma unroll
            for (int mi = 0; mi < 2; mi++) {
                uint32_t ro = (warp_m * 32 + mi * 16 + a_row) * ROWB + a_seg * 16 + kb;
                ldm_x4(ah[mi], Ah + ro);
                ldm_x4(al[mi], Al + ro);
            }
#pragma unroll
            for (int p = 0; p < 4; p++) {
                uint32_t r[4];
                uint32_t ro = (warp_n * 64 + p * 16 + b_row) * ROWB + b_seg * 16 + kb;
                ldm_x4(r, Bh + ro);
                bb[2 * p][0] = r[0]; bb[2 * p][1] = r[1];
                bb[2 * p + 1][0] = r[2]; bb[2 * p + 1][1] = r[3];
            }
#pragma unroll
            for (int mi = 0; mi < 2; mi++)
#pragma unroll
                for (int ni = 0; ni < 8; ni++) {
                    mma16816(acc[mi][ni], ah[mi], bb[ni]);
                    mma16816(acc[mi][ni], al[mi], bb[ni]);
                }
        }
        __syncthreads();
        if (c + 2 < 8) {
            fill_stage(sb + s * STAGE_BYTES, c + 2, m0, n0);
            asm volatile("cp.async.commit_group;" ::: "memory");
        }
    }

    // Epilogue: bias add + float2 stores
#pragma unroll
    for (int mi = 0; mi < 2; mi++) {
        size_t row0 = m0 + warp_m * 32 + mi * 16 + g;
#pragma unroll
        for (int ni = 0; ni < 8; ni++) {
            int col = n0 + warp_n * 64 + ni * 8 + 2 * t;
            float2 bv = *(const float2*)(bias + col);
            float2 o0, o1;
            o0.x = acc[mi][ni][0] + bv.x;  o0.y = acc[mi][ni][1] + bv.y;
            o1.x = acc[mi][ni][2] + bv.x;  o1.y = acc[mi][ni][3] + bv.y;
            *(float2*)(g_gx + row0 * N_DIM + col) = o0;
            *(float2*)(g_gx + (row0 + 8) * N_DIM + col) = o1;
        }
    }
}

// ---------------------------------------------------------------------------
// Scan with 8-step block prefetch. One thread per (b,h) chain.
// ---------------------------------------------------------------------------
__device__ __forceinline__ float sigf(float x) {
    return __fdividef(1.f, 1.f + __expf(-x));
}
__device__ __forceinline__ float tanhf_fast(float x) {
    return __fdividef(2.f, 1.f + __expf(-2.f * x)) - 1.f;
}

#define SCAN_U 8
#define RS ((size_t)B_DIM * N_DIM)   // 49152 floats between timesteps

__global__ __launch_bounds__(128, 1)
void scan_kernel(const float* __restrict__ b_hh, const float* __restrict__ w_hh,
                 float* __restrict__ out, long long out_size) {
    const int idx = blockIdx.x * blockDim.x + threadIdx.x;  // 0..16383
    const int b = idx >> 8;
    const int h = idx & (H_DIM - 1);

    const float w_hr = w_hh[h];
    const float w_hz = w_hh[H_DIM + h];
    const float w_hn = w_hh[2 * H_DIM + h];
    const float b_hr = b_hh[h];
    const float b_hz = b_hh[H_DIM + h];
    const float b_hn = b_hh[2 * H_DIM + h];

    const float* gp = g_gx + (size_t)b * N_DIM + h;

    float cr[SCAN_U], cz[SCAN_U], cn[SCAN_U];
#pragma unroll
    for (int j = 0; j < SCAN_U; j++) {
        const float* p = gp + (size_t)j * RS;
        cr[j] = p[0]; cz[j] = p[H_DIM]; cn[j] = p[2 * H_DIM];
    }

    float hv = 0.f;
    const int NB = T_DIM / SCAN_U;   // 256
    for (int tb = 0; tb < NB; tb++) {
        float nr[SCAN_U], nz[SCAN_U], nn[SCAN_U];
        const bool more = (tb + 1 < NB);
        if (more) {
            const float* np = gp + (size_t)(tb + 1) * SCAN_U * RS;
#pragma unroll
            for (int j = 0; j < SCAN_U; j++) {
                const float* p = np + (size_t)j * RS;
                nr[j] = p[0]; nz[j] = p[H_DIM]; nn[j] = p[2 * H_DIM];
            }
        }
#pragma unroll
        for (int j = 0; j < SCAN_U; j++) {
            float r = sigf(cr[j] + w_hr * hv + b_hr);
            float z = sigf(cz[j] + w_hz * hv + b_hz);
            float n = tanhf_fast(cn[j] + r * (w_hn * hv + b_hn));
            hv = n + z * (hv - n);
            out[(size_t)(tb * SCAN_U + j) * (B_DIM * H_DIM) + idx] = hv;
        }
        if (more) {
#pragma unroll
            for (int j = 0; j < SCAN_U; j++) { cr[j] = nr[j]; cz[j] = nz[j]; cn[j] = nn[j]; }
        }
    }
    if (out_size > (long long)T_DIM * B_DIM * H_DIM)
        out[(size_t)T_DIM * B_DIM * H_DIM + idx] = hv;
}

// ---------------------------------------------------------------------------
// Launch
// ---------------------------------------------------------------------------
extern "C" void kernel_launch(void* const* d_in, const int* in_sizes, int n_in,
                              void* d_out, int out_size) {
    const float* x    = (const float*)d_in[0];   // [T, B, I]
    const float* W_ih = (const float*)d_in[1];   // [3H, I]
    const float* b_ih = (const float*)d_in[2];   // [3H]
    const float* b_hh = (const float*)d_in[3];   // [3H]
    const float* w_hh = (const float*)d_in[4];   // [3, H]
    float* out = (float*)d_out;

    convert_kernel<<<32960, 256>>>(x, W_ih);

    cudaFuncSetAttribute(gemm_hmma_kernel, cudaFuncAttributeMaxDynamicSharedMemorySize, GEMM_SMEM);
    dim3 grid(N_DIM / 128, M_DIM / 128);   // (6, 1024)
    gemm_hmma_kernel<<<grid, 256, GEMM_SMEM>>>(b_ih);

    scan_kernel<<<(B_DIM * H_DIM) / 128, 128>>>(b_hh, w_hh, out, (long long)out_size);
}

// round 5
// speedup vs baseline: 2.9312x; 1.1905x over previous
#include <cuda_runtime.h>
#include <cuda_fp16.h>
#include <cstdint>
#include <cstddef>

#define T_DIM 2048
#define B_DIM 64
#define I_DIM 256
#define H_DIM 256
#define M_DIM (T_DIM * B_DIM)   // 131072
#define N_DIM (3 * H_DIM)       // 768
#define K_DIM I_DIM             // 256

// ---------------------------------------------------------------------------
// Device scratch
// ---------------------------------------------------------------------------
__device__ float g_gx[(size_t)M_DIM * N_DIM];           // gate preacts (402 MB)
__device__ __half g_Xh[(size_t)M_DIM * K_DIM];          // fp16 of x
__device__ __half g_Wh[(size_t)N_DIM * K_DIM];          // fp16 of W_ih

// ---------------------------------------------------------------------------
// Helpers
// ---------------------------------------------------------------------------
__device__ __forceinline__ uint32_t smem_to_u32(const void* p) {
    uint32_t a;
    asm("{ .reg .u64 t; cvta.to.shared.u64 t, %1; cvt.u32.u64 %0, t; }" : "=r"(a) : "l"(p));
    return a;
}
__device__ __forceinline__ void cp16(uint32_t dst, const void* src) {
    asm volatile("cp.async.cg.shared.global [%0], [%1], 16;" :: "r"(dst), "l"(src));
}
__device__ __forceinline__ void ldm_x4(uint32_t* r, uint32_t addr) {
    asm volatile("ldmatrix.sync.aligned.m8n8.x4.shared.b16 {%0,%1,%2,%3}, [%4];"
        : "=r"(r[0]), "=r"(r[1]), "=r"(r[2]), "=r"(r[3]) : "r"(addr));
}
__device__ __forceinline__ void mma16816(float* c, const uint32_t* a, const uint32_t* b) {
    asm volatile(
        "mma.sync.aligned.m16n8k16.row.col.f32.f16.f16.f32 "
        "{%0,%1,%2,%3}, {%4,%5,%6,%7}, {%8,%9}, {%0,%1,%2,%3};"
        : "+f"(c[0]), "+f"(c[1]), "+f"(c[2]), "+f"(c[3])
        : "r"(a[0]), "r"(a[1]), "r"(a[2]), "r"(a[3]), "r"(b[0]), "r"(b[1]));
}

// ---------------------------------------------------------------------------
// Convert: x -> fp16, W -> fp16
// ---------------------------------------------------------------------------
__device__ __forceinline__ uint32_t pack_h2(__half a, __half b) {
    __half2 t(a, b);
    return *reinterpret_cast<uint32_t*>(&t);
}

__global__ void convert_kernel(const float* __restrict__ x, const float* __restrict__ W) {
    const int n1 = (M_DIM * K_DIM) / 4;   // x float4s
    const int n2 = (N_DIM * K_DIM) / 4;   // W float4s
    int idx = blockIdx.x * blockDim.x + threadIdx.x;
    if (idx < n1) {
        float4 v = ((const float4*)x)[idx];
        uint2 ho;
        ho.x = pack_h2(__float2half_rn(v.x), __float2half_rn(v.y));
        ho.y = pack_h2(__float2half_rn(v.z), __float2half_rn(v.w));
        ((uint2*)g_Xh)[idx] = ho;
    } else if (idx < n1 + n2) {
        int pos = idx - n1;
        float4 v = ((const float4*)W)[pos];
        uint2 ho;
        ho.x = pack_h2(__float2half_rn(v.x), __float2half_rn(v.y));
        ho.y = pack_h2(__float2half_rn(v.z), __float2half_rn(v.w));
        ((uint2*)g_Wh)[pos] = ho;
    }
}

// ---------------------------------------------------------------------------
// HMMA GEMM: gx = X @ W^T + b_ih, single-term fp16.
// CTA tile 128x128, BK=32, 8 warps (warp 32x64), 2-stage cp.async,
// ldmatrix.x4 fragment loads, 80B-padded rows (conflict-free).
// ---------------------------------------------------------------------------
#define ROWB 80                       // 64B data + 16B pad
#define TILE_BYTES (128 * ROWB)       // 10240
#define STAGE_BYTES (2 * TILE_BYTES)  // Ah, Bh = 20480
#define GEMM_SMEM (2 * STAGE_BYTES)   // 40960

__device__ __forceinline__ void fill_stage(uint32_t base, int c, size_t m0, int n0) {
    const int tid = threadIdx.x;
    const int k0 = c * 32;
#pragma unroll
    for (int i = 0; i < 2; i++) {
        int v = tid + (i << 8);          // 0..511
        int row = v >> 2, seg = v & 3;   // 128 rows x 4 16B-segments
        uint32_t so = row * ROWB + seg * 16;
        size_t aoff = (m0 + row) * K_DIM + k0 + seg * 8;
        size_t boff = (size_t)(n0 + row) * K_DIM + k0 + seg * 8;
        cp16(base + so, g_Xh + aoff);
        cp16(base + TILE_BYTES + so, g_Wh + boff);
    }
}

__global__ __launch_bounds__(256, 2)
void gemm_hmma_kernel(const float* __restrict__ bias) {
    extern __shared__ __align__(16) char smem[];
    uint32_t sb = smem_to_u32(smem);

    const int tid = threadIdx.x;
    const int wid = tid >> 5, lane = tid & 31;
    const int g = lane >> 2, t = lane & 3;
    const int warp_m = wid & 3;          // 4 M-slices of 32
    const int warp_n = wid >> 2;         // 2 N-slices of 64
    const size_t m0 = (size_t)blockIdx.y * 128;
    const int n0 = blockIdx.x * 128;

    const uint32_t a_row = (lane & 15);
    const uint32_t a_seg = (lane >> 4);
    const uint32_t b_row = (lane & 7) + ((lane >> 4) << 3);
    const uint32_t b_seg = (lane >> 3) & 1;

    float acc[2][8][4];
#pragma unroll
    for (int mi = 0; mi < 2; mi++)
#pragma unroll
        for (int ni = 0; ni < 8; ni++)
#pragma unroll
            for (int j = 0; j < 4; j++) acc[mi][ni][j] = 0.f;

    fill_stage(sb, 0, m0, n0);
    asm volatile("cp.async.commit_group;" ::: "memory");
    fill_stage(sb + STAGE_BYTES, 1, m0, n0);
    asm volatile("cp.async.commit_group;" ::: "memory");

    for (int c = 0; c < 8; c++) {
        const int s = c & 1;
        if (c < 6) asm volatile("cp.async.wait_group 1;" ::: "memory");
        else       asm volatile("cp.async.wait_group 0;" ::: "memory");
        __syncthreads();

        const uint32_t Ah = sb + s * STAGE_BYTES;
        const uint32_t Bh = Ah + TILE_BYTES;

#pragma unroll
        for (int ks = 0; ks < 2; ks++) {
            const int kb = ks * 32;      // 16 fp16 = 32B
            uint32_t ah[2][4], bb[8][2];
#pragma unroll
            for (int mi = 0; mi < 2; mi++) {
                uint32_t ro = (warp_m * 32 + mi * 16 + a_row) * ROWB + a_seg * 16 + kb;
                ldm_x4(ah[mi], Ah + ro);
            }
#pragma unroll
            for (int p = 0; p < 4; p++) {
                uint32_t r[4];
                uint32_t ro = (warp_n * 64 + p * 16 + b_row) * ROWB + b_seg * 16 + kb;
                ldm_x4(r, Bh + ro);
                bb[2 * p][0] = r[0]; bb[2 * p][1] = r[1];
                bb[2 * p + 1][0] = r[2]; bb[2 * p + 1][1] = r[3];
            }
#pragma unroll
            for (int mi = 0; mi < 2; mi++)
#pragma unroll
                for (int ni = 0; ni < 8; ni++)
                    mma16816(acc[mi][ni], ah[mi], bb[ni]);
        }
        __syncthreads();
        if (c + 2 < 8) {
            fill_stage(sb + s * STAGE_BYTES, c + 2, m0, n0);
            asm volatile("cp.async.commit_group;" ::: "memory");
        }
    }

    // Epilogue: bias add + float2 stores
#pragma unroll
    for (int mi = 0; mi < 2; mi++) {
        size_t row0 = m0 + warp_m * 32 + mi * 16 + g;
#pragma unroll
        for (int ni = 0; ni < 8; ni++) {
            int col = n0 + warp_n * 64 + ni * 8 + 2 * t;
            float2 bv = *(const float2*)(bias + col);
            float2 o0, o1;
            o0.x = acc[mi][ni][0] + bv.x;  o0.y = acc[mi][ni][1] + bv.y;
            o1.x = acc[mi][ni][2] + bv.x;  o1.y = acc[mi][ni][3] + bv.y;
            *(float2*)(g_gx + row0 * N_DIM + col) = o0;
            *(float2*)(g_gx + (row0 + 8) * N_DIM + col) = o1;
        }
    }
}

// ---------------------------------------------------------------------------
// Scan with 8-step block prefetch. One thread per (b,h) chain.
// ---------------------------------------------------------------------------
__device__ __forceinline__ float sigf(float x) {
    return __fdividef(1.f, 1.f + __expf(-x));
}
__device__ __forceinline__ float tanhf_fast(float x) {
    return __fdividef(2.f, 1.f + __expf(-2.f * x)) - 1.f;
}

#define SCAN_U 8
#define RS ((size_t)B_DIM * N_DIM)   // 49152 floats between timesteps

__global__ __launch_bounds__(128, 1)
void scan_kernel(const float* __restrict__ b_hh, const float* __restrict__ w_hh,
                 float* __restrict__ out, long long out_size) {
    const int idx = blockIdx.x * blockDim.x + threadIdx.x;  // 0..16383
    const int b = idx >> 8;
    const int h = idx & (H_DIM - 1);

    const float w_hr = w_hh[h];
    const float w_hz = w_hh[H_DIM + h];
    const float w_hn = w_hh[2 * H_DIM + h];
    const float b_hr = b_hh[h];
    const float b_hz = b_hh[H_DIM + h];
    const float b_hn = b_hh[2 * H_DIM + h];

    const float* gp = g_gx + (size_t)b * N_DIM + h;

    float cr[SCAN_U], cz[SCAN_U], cn[SCAN_U];
#pragma unroll
    for (int j = 0; j < SCAN_U; j++) {
        const float* p = gp + (size_t)j * RS;
        cr[j] = p[0]; cz[j] = p[H_DIM]; cn[j] = p[2 * H_DIM];
    }

    float hv = 0.f;
    const int NB = T_DIM / SCAN_U;   // 256
    for (int tb = 0; tb < NB; tb++) {
        float nr[SCAN_U], nz[SCAN_U], nn[SCAN_U];
        const bool more = (tb + 1 < NB);
        if (more) {
            const float* np = gp + (size_t)(tb + 1) * SCAN_U * RS;
#pragma unroll
            for (int j = 0; j < SCAN_U; j++) {
                const float* p = np + (size_t)j * RS;
                nr[j] = p[0]; nz[j] = p[H_DIM]; nn[j] = p[2 * H_DIM];
            }
        }
#pragma unroll
        for (int j = 0; j < SCAN_U; j++) {
            float r = sigf(cr[j] + w_hr * hv + b_hr);
            float z = sigf(cz[j] + w_hz * hv + b_hz);
            float n = tanhf_fast(cn[j] + r * (w_hn * hv + b_hn));
            hv = n + z * (hv - n);
            out[(size_t)(tb * SCAN_U + j) * (B_DIM * H_DIM) + idx] = hv;
        }
        if (more) {
#pragma unroll
            for (int j = 0; j < SCAN_U; j++) { cr[j] = nr[j]; cz[j] = nz[j]; cn[j] = nn[j]; }
        }
    }
    if (out_size > (long long)T_DIM * B_DIM * H_DIM)
        out[(size_t)T_DIM * B_DIM * H_DIM + idx] = hv;
}

// ---------------------------------------------------------------------------
// Launch
// ---------------------------------------------------------------------------
extern "C" void kernel_launch(void* const* d_in, const int* in_sizes, int n_in,
                              void* d_out, int out_size) {
    const float* x    = (const float*)d_in[0];   // [T, B, I]
    const float* W_ih = (const float*)d_in[1];   // [3H, I]
    const float* b_ih = (const float*)d_in[2];   // [3H]
    const float* b_hh = (const float*)d_in[3];   // [3H]
    const float* w_hh = (const float*)d_in[4];   // [3, H]
    float* out = (float*)d_out;

    convert_kernel<<<32960, 256>>>(x, W_ih);

    cudaFuncSetAttribute(gemm_hmma_kernel, cudaFuncAttributeMaxDynamicSharedMemorySize, GEMM_SMEM);
    dim3 grid(N_DIM / 128, M_DIM / 128);   // (6, 1024)
    gemm_hmma_kernel<<<grid, 256, GEMM_SMEM>>>(b_ih);

    scan_kernel<<<(B_DIM * H_DIM) / 128, 128>>>(b_hh, w_hh, out, (long long)out_size);
}